// round 2
// baseline (speedup 1.0000x reference)
#include <cuda_runtime.h>
#include <cstdint>

// ---------------------------------------------------------------------------
// HOSVD aggregator, restructured:
//   ris[n,d,r] = sum_i x[n,d,i] * U_stack[d,i,r]
//   P[n, j=g0*8+g4] = ris0[g0]*ris1[g4]        (g4 = m4)
//   Q[n, k=g2*8+g3] = ris3[g2]*ris2[g3]        (g2 = m2, g3 = m3)
//   G3[m1,k,j]      = G[g0,m1,g2,g3,g4]
//   v[n,m1] = sum_k Q[n,k] * sum_j P[n,j]*G3[m1,k,j]
//   out[n,o] = sum_m1 v[n,m1] * U_output[m1,o]
// ---------------------------------------------------------------------------

#define MAXN 65536

__device__ float g_P [(size_t)MAXN * 64];
__device__ float g_Q [(size_t)MAXN * 64];
__device__ float g_G3[32768];
__device__ float g_Ut[8192];

// ---------------------------------------------------------------------------
// prep: permute G -> G3, transpose U_stack -> U_t[d][r][i]
// ---------------------------------------------------------------------------
__global__ void prep_kernel(const float* __restrict__ G,
                            const float* __restrict__ U) {
    int t = blockIdx.x * blockDim.x + threadIdx.x;
    if (t < 32768) {
        int m1 = t >> 12;
        int k  = (t >> 6) & 63;
        int j  = t & 63;
        int g0 = j >> 3, g4 = j & 7;
        int g2 = k >> 3, g3i = k & 7;
        g_G3[t] = G[g0 * 4096 + m1 * 512 + g2 * 64 + g3i * 8 + g4];
    }
    if (t < 8192) {
        int d = t >> 11;
        int r = (t >> 8) & 7;
        int i = t & 255;
        g_Ut[t] = U[d * 2048 + i * 8 + r];
    }
}

// ---------------------------------------------------------------------------
// kA: warp per sample. Projection + outer products -> P, Q (64 each).
// smem: U_t (8192 f) + per-warp reduce buffers 8*32*33 f
// ---------------------------------------------------------------------------
__global__ void __launch_bounds__(256) proj_kernel(
        const float* __restrict__ X, int N) {
    extern __shared__ float sm[];
    float* Ut  = sm;              // 8192 floats
    float* red = sm + 8192;       // 8 * 32*33 floats

    int tid = threadIdx.x;
    int w   = tid >> 5;
    int l   = tid & 31;

    for (int i = tid; i < 8192; i += 256) Ut[i] = g_Ut[i];
    __syncthreads();

    const float4* Ut4  = (const float4*)Ut;
    float*        myred = red + w * (32 * 33);
    int warpsTotal = gridDim.x * 8;

    for (int n = blockIdx.x * 8 + w; n < N; n += warpsTotal) {
        const float4* X4 = (const float4*)X + (size_t)n * 256;
        float4 a[8];
#pragma unroll
        for (int q = 0; q < 8; q++) a[q] = X4[q * 32 + l];

        float p[32];
#pragma unroll
        for (int t = 0; t < 32; t++) p[t] = 0.f;

#pragma unroll
        for (int q = 0; q < 8; q++) {
            const int d    = q >> 1;
            const int base = ((q & 1) << 5) + l;   // float4 index inside d's 256 floats
#pragma unroll
            for (int r = 0; r < 8; r++) {
                float4 u = Ut4[(d * 8 + r) * 64 + base];
                p[d * 8 + r] += a[q].x * u.x + a[q].y * u.y
                              + a[q].z * u.z + a[q].w * u.w;
            }
        }

        // cross-lane reduce: lane t ends up holding total ris[t>>3][t&7]
#pragma unroll
        for (int t = 0; t < 32; t++) myred[t * 33 + l] = p[t];
        __syncwarp();
        float s = 0.f;
#pragma unroll
        for (int i = 0; i < 32; i++) s += myred[l * 33 + i];

        // gather the needed ris entries via shuffle
        float r0a = __shfl_sync(0xffffffffu, s, (l >> 3));          // ris0[g0],   g0 = l>>3
        float r0b = __shfl_sync(0xffffffffu, s, 4 + (l >> 3));      // ris0[g0+4]
        float r1  = __shfl_sync(0xffffffffu, s, 8  + (l & 7));      // ris1[g4],   g4 = l&7
        float r3a = __shfl_sync(0xffffffffu, s, 24 + (l >> 3));     // ris3[g2],   g2 = l>>3
        float r3b = __shfl_sync(0xffffffffu, s, 28 + (l >> 3));     // ris3[g2+4]
        float r2  = __shfl_sync(0xffffffffu, s, 16 + (l & 7));      // ris2[g3],   g3 = l&7

        float* Pp = g_P + (size_t)n * 64;
        float* Qp = g_Q + (size_t)n * 64;
        Pp[l]      = r0a * r1;   // j = l       : g0 = l>>3,     g4 = l&7
        Pp[l + 32] = r0b * r1;   // j = l+32    : g0 = 4+(l>>3), g4 = l&7
        Qp[l]      = r3a * r2;   // k = l       : g2 = l>>3,     g3 = l&7
        Qp[l + 32] = r3b * r2;   // k = l+32    : g2 = 4+(l>>3), g3 = l&7

        __syncwarp();   // protect myred reuse next iteration
    }
}

// ---------------------------------------------------------------------------
// kB: lane per sample. G3 resident in SMEM (broadcast LDS), P in registers.
// Fused epilogue: v @ U_output with SMEM transpose for coalesced stores.
// smem: G3 (32768 f) + Uo (1024 f) + vbuf (16*32*8 f)
// ---------------------------------------------------------------------------
__global__ void __launch_bounds__(512) core_kernel(
        const float* __restrict__ Uo,
        float* __restrict__ out, int N) {
    extern __shared__ float sm[];
    float* G3s = sm;                 // 32768
    float* Uos = sm + 32768;         // 1024
    float* vb  = sm + 33792;         // 16*32*8 = 4096

    int tid = threadIdx.x;
    int w   = tid >> 5;
    int l   = tid & 31;

    for (int i = tid; i < 32768; i += 512) G3s[i] = g_G3[i];
    for (int i = tid; i < 1024;  i += 512) Uos[i] = Uo[i];
    __syncthreads();

    const float4* G34 = (const float4*)G3s;
    const float4* Uo4 = (const float4*)Uos;
    float* myv = vb + w * 256;

    int ntasks  = (N + 31) >> 5;
    int tstride = gridDim.x * 16;

    for (int task = blockIdx.x * 16 + w; task < ntasks; task += tstride) {
        int n  = task * 32 + l;
        int nc = (n < N) ? n : (N - 1);

        float4 pa[16];
        const float4* Pp = (const float4*)g_P + (size_t)nc * 16;
#pragma unroll
        for (int jj = 0; jj < 16; jj++) pa[jj] = Pp[jj];

        const float* Qp = g_Q + (size_t)nc * 64;

        float v[8];
#pragma unroll
        for (int m = 0; m < 8; m++) v[m] = 0.f;

        for (int k = 0; k < 64; k++) {
            float qk = __ldg(Qp + k);
#pragma unroll
            for (int m = 0; m < 8; m++) {
                const float4* grow = G34 + m * 1024 + k * 16;
                float t0 = 0.f, t1 = 0.f, t2 = 0.f, t3 = 0.f;
#pragma unroll
                for (int jj = 0; jj < 16; jj++) {
                    float4 g = grow[jj];
                    t0 += pa[jj].x * g.x;
                    t1 += pa[jj].y * g.y;
                    t2 += pa[jj].z * g.z;
                    t3 += pa[jj].w * g.w;
                }
                v[m] += ((t0 + t1) + (t2 + t3)) * qk;
            }
        }

        // epilogue: out[n,:] = v @ Uo, via smem transpose for coalesced f4 stores
#pragma unroll
        for (int m = 0; m < 8; m++) myv[l * 8 + m] = v[m];
        __syncwarp();

        for (int s = 0; s < 32; s++) {
            int ns = task * 32 + s;
            if (ns >= N) break;
            float4 acc = make_float4(0.f, 0.f, 0.f, 0.f);
#pragma unroll
            for (int m = 0; m < 8; m++) {
                float  vs = myv[s * 8 + m];
                float4 u  = Uo4[m * 32 + l];
                acc.x += vs * u.x; acc.y += vs * u.y;
                acc.z += vs * u.z; acc.w += vs * u.w;
            }
            ((float4*)out)[(size_t)ns * 32 + l] = acc;
        }
        __syncwarp();
    }
}

// ---------------------------------------------------------------------------
extern "C" void kernel_launch(void* const* d_in, const int* in_sizes, int n_in,
                              void* d_out, int out_size) {
    const float* X  = (const float*)d_in[0];   // [N,4,256]
    const float* G  = (const float*)d_in[1];   // [8,8,8,8,8]
    const float* U  = (const float*)d_in[2];   // [4,256,8]
    const float* Uo = (const float*)d_in[3];   // [8,128]
    float* out = (float*)d_out;

    int N = in_sizes[0] / 1024;
    if (N > MAXN) N = MAXN;

    // prep
    prep_kernel<<<128, 256>>>(G, U);

    // projection
    const int kA_smem = (8192 + 8 * 32 * 33) * (int)sizeof(float);   // ~66 KB
    cudaFuncSetAttribute(proj_kernel,
                         cudaFuncAttributeMaxDynamicSharedMemorySize, kA_smem);
    proj_kernel<<<444, 256, kA_smem>>>(X, N);

    // core contraction + output
    const int kB_smem = (32768 + 1024 + 4096) * (int)sizeof(float);  // ~148 KB
    cudaFuncSetAttribute(core_kernel,
                         cudaFuncAttributeMaxDynamicSharedMemorySize, kB_smem);
    core_kernel<<<148, 512, kB_smem>>>(Uo, out, N);
}

// round 3
// speedup vs baseline: 1.1994x; 1.1994x over previous
#include <cuda_runtime.h>
#include <cstdint>

// ---------------------------------------------------------------------------
// HOSVD aggregator:
//   ris[n,d,r] = sum_i x[n,d,i] * U_stack[d,i,r]
//   P[n, j=g0*8+g4] = ris0[g0]*ris1[g4]
//   Q[n, k=g2*8+g3] = ris3[g2]*ris2[g3]
//   G3[m1,k,j]      = G[g0,m1,g2,g3,g4]
//   v[n,m1] = sum_k Q[n,k] * sum_j P[n,j]*G3[m1,k,j]     <-- f32x2 packed
//   out[n,o] = sum_m1 v[n,m1] * U_output[m1,o]
// ---------------------------------------------------------------------------

#define MAXN 65536

__device__ float g_P [(size_t)MAXN * 64];
__device__ float g_Q [(size_t)MAXN * 64];
__device__ float g_G3[32768];
__device__ float g_Ut[8192];

// packed f32x2 helpers (sm_100+)
#define FMA_F32X2(d, a, b, c) \
    asm("fma.rn.f32x2 %0, %1, %2, %3;" : "=l"(d) : "l"(a), "l"(b), "l"(c))
#define ADD_F32X2M(d, a, b) \
    asm("add.rn.f32x2 %0, %1, %2;" : "=l"(d) : "l"(a), "l"(b))
#define PACK_F32X2M(d, lo, hi) \
    asm("mov.b64 %0, {%1, %2};" : "=l"(d) : "f"(lo), "f"(hi))
#define UNPACK_F32X2M(lo, hi, s) \
    asm("mov.b64 {%0, %1}, %2;" : "=f"(lo), "=f"(hi) : "l"(s))

// ---------------------------------------------------------------------------
// prep: permute G -> G3, transpose U_stack -> U_t[d][r][i]
// ---------------------------------------------------------------------------
__global__ void prep_kernel(const float* __restrict__ G,
                            const float* __restrict__ U) {
    int t = blockIdx.x * blockDim.x + threadIdx.x;
    if (t < 32768) {
        int m1 = t >> 12;
        int k  = (t >> 6) & 63;
        int j  = t & 63;
        int g0 = j >> 3, g4 = j & 7;
        int g2 = k >> 3, g3i = k & 7;
        g_G3[t] = G[g0 * 4096 + m1 * 512 + g2 * 64 + g3i * 8 + g4];
    }
    if (t < 8192) {
        int d = t >> 11;
        int r = (t >> 8) & 7;
        int i = t & 255;
        g_Ut[t] = U[d * 2048 + i * 8 + r];
    }
}

// ---------------------------------------------------------------------------
// kA: warp per sample. Projection + outer products -> P, Q (64 each).
// ---------------------------------------------------------------------------
__global__ void __launch_bounds__(256) proj_kernel(
        const float* __restrict__ X, int N) {
    extern __shared__ float sm[];
    float* Ut  = sm;              // 8192 floats
    float* red = sm + 8192;       // 8 * 32*33 floats

    int tid = threadIdx.x;
    int w   = tid >> 5;
    int l   = tid & 31;

    for (int i = tid; i < 8192; i += 256) Ut[i] = g_Ut[i];
    __syncthreads();

    const float4* Ut4   = (const float4*)Ut;
    float*        myred = red + w * (32 * 33);
    int warpsTotal = gridDim.x * 8;

    for (int n = blockIdx.x * 8 + w; n < N; n += warpsTotal) {
        const float4* X4 = (const float4*)X + (size_t)n * 256;
        float4 a[8];
#pragma unroll
        for (int q = 0; q < 8; q++) a[q] = X4[q * 32 + l];

        float p[32];
#pragma unroll
        for (int t = 0; t < 32; t++) p[t] = 0.f;

#pragma unroll
        for (int q = 0; q < 8; q++) {
            const int d    = q >> 1;
            const int base = ((q & 1) << 5) + l;
#pragma unroll
            for (int r = 0; r < 8; r++) {
                float4 u = Ut4[(d * 8 + r) * 64 + base];
                p[d * 8 + r] += a[q].x * u.x + a[q].y * u.y
                              + a[q].z * u.z + a[q].w * u.w;
            }
        }

#pragma unroll
        for (int t = 0; t < 32; t++) myred[t * 33 + l] = p[t];
        __syncwarp();
        float s = 0.f;
#pragma unroll
        for (int i = 0; i < 32; i++) s += myred[l * 33 + i];
        // lane t = d*8+r holds ris[d][r]

        float r0a = __shfl_sync(0xffffffffu, s, (l >> 3));
        float r0b = __shfl_sync(0xffffffffu, s, 4 + (l >> 3));
        float r1  = __shfl_sync(0xffffffffu, s, 8  + (l & 7));
        float r3a = __shfl_sync(0xffffffffu, s, 24 + (l >> 3));
        float r3b = __shfl_sync(0xffffffffu, s, 28 + (l >> 3));
        float r2  = __shfl_sync(0xffffffffu, s, 16 + (l & 7));

        float* Pp = g_P + (size_t)n * 64;
        float* Qp = g_Q + (size_t)n * 64;
        Pp[l]      = r0a * r1;
        Pp[l + 32] = r0b * r1;
        Qp[l]      = r3a * r2;
        Qp[l + 32] = r3b * r2;

        __syncwarp();
    }
}

// ---------------------------------------------------------------------------
// kB: lane per sample, packed f32x2 inner contraction.
// smem: G3 (32768 f) + Uo (1024 f) + vbuf (12*256 f)
// ---------------------------------------------------------------------------
__global__ void __launch_bounds__(384) core_kernel(
        const float* __restrict__ Uo,
        float* __restrict__ out, int N) {
    extern __shared__ float sm[];
    float* G3s = sm;                 // 32768
    float* Uos = sm + 32768;         // 1024
    float* vb  = sm + 33792;         // 12*256 = 3072

    int tid = threadIdx.x;
    int w   = tid >> 5;
    int l   = tid & 31;

    for (int i = tid; i < 32768; i += 384) G3s[i] = g_G3[i];
    for (int i = tid; i < 1024;  i += 384) Uos[i] = Uo[i];
    __syncthreads();

    const ulonglong2* G3v = (const ulonglong2*)G3s;   // 4 floats / elem
    const float4*     Uo4 = (const float4*)Uos;
    float* myv = vb + w * 256;

    int ntasks  = (N + 31) >> 5;
    int tstride = gridDim.x * 12;

    for (int task = blockIdx.x * 12 + w; task < ntasks; task += tstride) {
        int n  = task * 32 + l;
        int nc = (n < N) ? n : (N - 1);

        // load this lane's P row as 32 packed f32x2 operands
        unsigned long long pa2[32];
        const ulonglong2* Pp = (const ulonglong2*)(g_P + (size_t)nc * 64);
#pragma unroll
        for (int i = 0; i < 16; i++) {
            ulonglong2 t = Pp[i];
            pa2[2 * i]     = t.x;
            pa2[2 * i + 1] = t.y;
        }

        const float* Qp = g_Q + (size_t)nc * 64;

        unsigned long long v2[8];
#pragma unroll
        for (int m = 0; m < 8; m++) v2[m] = 0ull;

        for (int k = 0; k < 64; k++) {
            float qk = __ldg(Qp + k);
            unsigned long long qk2;
            PACK_F32X2M(qk2, qk, qk);
#pragma unroll
            for (int m = 0; m < 8; m++) {
                const ulonglong2* grow = G3v + m * 1024 + k * 16;
                unsigned long long acc0 = 0ull, acc1 = 0ull;
#pragma unroll
                for (int jj = 0; jj < 16; jj++) {
                    ulonglong2 g = grow[jj];
                    FMA_F32X2(acc0, pa2[2 * jj],     g.x, acc0);
                    FMA_F32X2(acc1, pa2[2 * jj + 1], g.y, acc1);
                }
                unsigned long long s01;
                ADD_F32X2M(s01, acc0, acc1);
                FMA_F32X2(v2[m], s01, qk2, v2[m]);
            }
        }

        // epilogue: out[n,:] = v @ Uo via smem transpose, coalesced f4 stores
#pragma unroll
        for (int m = 0; m < 8; m++) {
            float lo, hi;
            UNPACK_F32X2M(lo, hi, v2[m]);
            myv[l * 8 + m] = lo + hi;
        }
        __syncwarp();

        for (int s = 0; s < 32; s++) {
            int ns = task * 32 + s;
            if (ns >= N) break;
            float4 acc = make_float4(0.f, 0.f, 0.f, 0.f);
#pragma unroll
            for (int m = 0; m < 8; m++) {
                float  vs = myv[s * 8 + m];
                float4 u  = Uo4[m * 32 + l];
                acc.x += vs * u.x; acc.y += vs * u.y;
                acc.z += vs * u.z; acc.w += vs * u.w;
            }
            ((float4*)out)[(size_t)ns * 32 + l] = acc;
        }
        __syncwarp();
    }
}

// ---------------------------------------------------------------------------
extern "C" void kernel_launch(void* const* d_in, const int* in_sizes, int n_in,
                              void* d_out, int out_size) {
    const float* X  = (const float*)d_in[0];   // [N,4,256]
    const float* G  = (const float*)d_in[1];   // [8,8,8,8,8]
    const float* U  = (const float*)d_in[2];   // [4,256,8]
    const float* Uo = (const float*)d_in[3];   // [8,128]
    float* out = (float*)d_out;

    int N = in_sizes[0] / 1024;
    if (N > MAXN) N = MAXN;

    prep_kernel<<<128, 256>>>(G, U);

    const int kA_smem = (8192 + 8 * 32 * 33) * (int)sizeof(float);
    cudaFuncSetAttribute(proj_kernel,
                         cudaFuncAttributeMaxDynamicSharedMemorySize, kA_smem);
    proj_kernel<<<444, 256, kA_smem>>>(X, N);

    const int kB_smem = (32768 + 1024 + 3072) * (int)sizeof(float);
    cudaFuncSetAttribute(core_kernel,
                         cudaFuncAttributeMaxDynamicSharedMemorySize, kB_smem);
    core_kernel<<<148, 384, kB_smem>>>(Uo, out, N);
}

// round 6
// speedup vs baseline: 1.3229x; 1.1030x over previous
#include <cuda_runtime.h>
#include <cstdint>

// ---------------------------------------------------------------------------
// HOSVD aggregator, rank-1 factored core:
//   ris[n,d,r] = sum_i x[n,d,i] * U_stack[d,i,r]          (proj)
//   P[n,j=g0*8+g4] = ris0[g0]*ris1[g4]   (built in regs, 32 f32x2)
//   q[n,k=g2*8+g3] = ris3[g2]*ris2[g3]   (built per-k from regs)
//   G3[m1,k,j]     = G[g0,m1,g2,g3,g4]
//   V[n,m1] = sum_k q_k * sum_j P_j * G3[m1,k,j]          (core, f32x2)
//   out[n,o] = sum_m1 V[n,m1] * U_output[m1,o]            (vout)
// ---------------------------------------------------------------------------

#define MAXN 65536

__device__ float g_R [(size_t)MAXN * 32];   // per-sample ris (4x8)
__device__ float g_V [(size_t)MAXN * 8];    // per-sample v[m1]
__device__ float g_G3[32768];
__device__ float g_Ut[8192];

#define FMA2(d, a, b, c) \
    asm("fma.rn.f32x2 %0, %1, %2, %3;" : "=l"(d) : "l"(a), "l"(b), "l"(c))
#define MUL2(d, a, b) \
    asm("mul.rn.f32x2 %0, %1, %2;" : "=l"(d) : "l"(a), "l"(b))
#define ADD2(d, a, b) \
    asm("add.rn.f32x2 %0, %1, %2;" : "=l"(d) : "l"(a), "l"(b))
#define PACK2(d, lo, hi) \
    asm("mov.b64 %0, {%1, %2};" : "=l"(d) : "f"(lo), "f"(hi))
#define UNPACK2(lo, hi, s) \
    asm("mov.b64 {%0, %1}, %2;" : "=f"(lo), "=f"(hi) : "l"(s))

// ---------------------------------------------------------------------------
// prep: permute G -> G3, transpose U_stack -> U_t[d][r][i]
// ---------------------------------------------------------------------------
__global__ void prep_kernel(const float* __restrict__ G,
                            const float* __restrict__ U) {
    int t = blockIdx.x * blockDim.x + threadIdx.x;
    if (t < 32768) {
        int m1 = t >> 12;
        int k  = (t >> 6) & 63;
        int j  = t & 63;
        int g0 = j >> 3, g4 = j & 7;
        int g2 = k >> 3, g3i = k & 7;
        g_G3[t] = G[g0 * 4096 + m1 * 512 + g2 * 64 + g3i * 8 + g4];
    }
    if (t < 8192) {
        int d = t >> 11;
        int r = (t >> 8) & 7;
        int i = t & 255;
        g_Ut[t] = U[d * 2048 + i * 8 + r];
    }
}

// ---------------------------------------------------------------------------
// proj: warp per sample -> ris (32 floats per sample)
// ---------------------------------------------------------------------------
__global__ void __launch_bounds__(256) proj_kernel(
        const float* __restrict__ X, int N) {
    extern __shared__ float sm[];
    float* Ut  = sm;              // 8192 floats
    float* red = sm + 8192;       // 8 * 32*33 floats

    int tid = threadIdx.x;
    int w   = tid >> 5;
    int l   = tid & 31;

    for (int i = tid; i < 8192; i += 256) Ut[i] = g_Ut[i];
    __syncthreads();

    const float4* Ut4   = (const float4*)Ut;
    float*        myred = red + w * (32 * 33);
    int warpsTotal = gridDim.x * 8;

    for (int n = blockIdx.x * 8 + w; n < N; n += warpsTotal) {
        const float4* X4 = (const float4*)X + (size_t)n * 256;
        float4 a[8];
#pragma unroll
        for (int q = 0; q < 8; q++) a[q] = X4[q * 32 + l];

        float p[32];
#pragma unroll
        for (int t = 0; t < 32; t++) p[t] = 0.f;

#pragma unroll
        for (int q = 0; q < 8; q++) {
            const int d    = q >> 1;
            const int base = ((q & 1) << 5) + l;
#pragma unroll
            for (int r = 0; r < 8; r++) {
                float4 u = Ut4[(d * 8 + r) * 64 + base];
                p[d * 8 + r] += a[q].x * u.x + a[q].y * u.y
                              + a[q].z * u.z + a[q].w * u.w;
            }
        }

#pragma unroll
        for (int t = 0; t < 32; t++) myred[t * 33 + l] = p[t];
        __syncwarp();
        float s = 0.f;
#pragma unroll
        for (int i = 0; i < 32; i++) s += myred[l * 33 + i];
        // lane l = d*8+r holds ris[d][r]

        g_R[(size_t)n * 32 + l] = s;
        __syncwarp();
    }
}

// ---------------------------------------------------------------------------
// core: lane per sample, quarter-task = (32-sample block, m-pair).
// G3 in smem (broadcast LDS.128), P/q built in registers from ris.
// smem: G3 (32768 f) + r3 staging (16 warps * 256 f)
// ---------------------------------------------------------------------------
__global__ void __launch_bounds__(512) core_kernel(int N) {
    extern __shared__ float sm[];
    float* G3s = sm;                 // 32768 floats
    float* r3s = sm + 32768;         // 16 * 256 floats

    int tid = threadIdx.x;
    int w   = tid >> 5;
    int l   = tid & 31;

    for (int i = tid; i < 32768; i += 512) G3s[i] = g_G3[i];
    __syncthreads();

    const ulonglong2* G3v = (const ulonglong2*)G3s;   // 4 floats / elem
    float* myr3 = r3s + w * 256;

    int nblocks = (N + 31) >> 5;
    int ntasks  = nblocks * 4;                        // 4 m-pairs per block
    int tstride = gridDim.x * 16;

    for (int task = blockIdx.x + gridDim.x * w; task < ntasks; task += tstride) {
        int sb = task >> 2;          // sample block
        int q  = task & 3;           // m-quarter
        int m0 = q * 2;

        int n  = sb * 32 + l;
        int nc = (n < N) ? n : (N - 1);

        // load this lane's ris (32 floats)
        float4 risv[8];
        const float4* Rp = (const float4*)(g_R + (size_t)nc * 32);
#pragma unroll
        for (int i = 0; i < 8; i++) risv[i] = __ldg(Rp + i);

        const float ris0[8] = { risv[0].x, risv[0].y, risv[0].z, risv[0].w,
                                risv[1].x, risv[1].y, risv[1].z, risv[1].w };
        const float ris1[8] = { risv[2].x, risv[2].y, risv[2].z, risv[2].w,
                                risv[3].x, risv[3].y, risv[3].z, risv[3].w };
        const float ris2[8] = { risv[4].x, risv[4].y, risv[4].z, risv[4].w,
                                risv[5].x, risv[5].y, risv[5].z, risv[5].w };
        const float ris3[8] = { risv[6].x, risv[6].y, risv[6].z, risv[6].w,
                                risv[7].x, risv[7].y, risv[7].z, risv[7].w };

        // stage ris3 (dynamically indexed by g2 loop) in smem
#pragma unroll
        for (int g2 = 0; g2 < 8; g2++) myr3[g2 * 32 + l] = ris3[g2];
        __syncwarp();

        // build P = ris0 (x) ris1 as 32 f32x2 pairs, and r2 dup-pairs
        unsigned long long rp1[4], r2d[8], pa2[32];
#pragma unroll
        for (int t = 0; t < 4; t++) PACK2(rp1[t], ris1[2 * t], ris1[2 * t + 1]);
#pragma unroll
        for (int g3 = 0; g3 < 8; g3++) PACK2(r2d[g3], ris2[g3], ris2[g3]);
#pragma unroll
        for (int g0 = 0; g0 < 8; g0++) {
            unsigned long long r0d;
            PACK2(r0d, ris0[g0], ris0[g0]);
#pragma unroll
            for (int t = 0; t < 4; t++) MUL2(pa2[g0 * 4 + t], r0d, rp1[t]);
        }

        unsigned long long v2[2];
        v2[0] = 0ull; v2[1] = 0ull;

        for (int g2 = 0; g2 < 8; g2++) {
            float r3c = myr3[g2 * 32 + l];
            unsigned long long r3d;
            PACK2(r3d, r3c, r3c);
#pragma unroll
            for (int g3 = 0; g3 < 8; g3++) {
                int k = g2 * 8 + g3;
                unsigned long long qk2;
                MUL2(qk2, r3d, r2d[g3]);
#pragma unroll
                for (int m = 0; m < 2; m++) {
                    const ulonglong2* gp = G3v + (m0 + m) * 1024 + k * 16;
                    unsigned long long c0 = 0ull, c1 = 0ull,
                                       c2 = 0ull, c3 = 0ull;
#pragma unroll
                    for (int t = 0; t < 4; t++) {
                        ulonglong2 ga = gp[t];
                        FMA2(c0, pa2[2 * t],      ga.x, c0);
                        FMA2(c0, pa2[2 * t + 1],  ga.y, c0);
                        ulonglong2 gb = gp[4 + t];
                        FMA2(c1, pa2[8 + 2 * t],     gb.x, c1);
                        FMA2(c1, pa2[8 + 2 * t + 1], gb.y, c1);
                        ulonglong2 gc = gp[8 + t];
                        FMA2(c2, pa2[16 + 2 * t],     gc.x, c2);
                        FMA2(c2, pa2[16 + 2 * t + 1], gc.y, c2);
                        ulonglong2 gd = gp[12 + t];
                        FMA2(c3, pa2[24 + 2 * t],     gd.x, c3);
                        FMA2(c3, pa2[24 + 2 * t + 1], gd.y, c3);
                    }
                    unsigned long long s01, s23, s;
                    ADD2(s01, c0, c1);
                    ADD2(s23, c2, c3);
                    ADD2(s, s01, s23);
                    FMA2(v2[m], s, qk2, v2[m]);
                }
            }
        }

        float lo0, hi0, lo1, hi1;
        UNPACK2(lo0, hi0, v2[0]);
        UNPACK2(lo1, hi1, v2[1]);
        float2 vout = make_float2(lo0 + hi0, lo1 + hi1);
        *(float2*)(g_V + (size_t)nc * 8 + m0) = vout;

        __syncwarp();   // myr3 reuse next task
    }
}

// ---------------------------------------------------------------------------
// vout: out[n,:] = V[n,:] @ Uo   (memory-bound, coalesced)
// ---------------------------------------------------------------------------
__global__ void __launch_bounds__(256) vout_kernel(
        const float* __restrict__ Uo,
        float* __restrict__ out, int N) {
    __shared__ float Uos[1024];
    int tid = threadIdx.x;
    for (int i = tid; i < 1024; i += 256) Uos[i] = Uo[i];
    __syncthreads();

    const float4* Uo4 = (const float4*)Uos;
    int n  = blockIdx.x * 8 + (tid >> 5);
    int o4 = tid & 31;
    if (n >= N) return;

    const float4* vp = (const float4*)(g_V + (size_t)n * 8);
    float4 va = __ldg(vp);
    float4 vb = __ldg(vp + 1);
    float vm[8] = { va.x, va.y, va.z, va.w, vb.x, vb.y, vb.z, vb.w };

    float4 acc = make_float4(0.f, 0.f, 0.f, 0.f);
#pragma unroll
    for (int m = 0; m < 8; m++) {
        float4 u = Uo4[m * 32 + o4];
        acc.x += vm[m] * u.x; acc.y += vm[m] * u.y;
        acc.z += vm[m] * u.z; acc.w += vm[m] * u.w;
    }
    ((float4*)out)[(size_t)n * 32 + o4] = acc;
}

// ---------------------------------------------------------------------------
extern "C" void kernel_launch(void* const* d_in, const int* in_sizes, int n_in,
                              void* d_out, int out_size) {
    const float* X  = (const float*)d_in[0];   // [N,4,256]
    const float* G  = (const float*)d_in[1];   // [8,8,8,8,8]
    const float* U  = (const float*)d_in[2];   // [4,256,8]
    const float* Uo = (const float*)d_in[3];   // [8,128]
    float* out = (float*)d_out;

    int N = in_sizes[0] / 1024;
    if (N > MAXN) N = MAXN;

    prep_kernel<<<128, 256>>>(G, U);

    const int kA_smem = (8192 + 8 * 32 * 33) * (int)sizeof(float);
    cudaFuncSetAttribute(proj_kernel,
                         cudaFuncAttributeMaxDynamicSharedMemorySize, kA_smem);
    proj_kernel<<<444, 256, kA_smem>>>(X, N);

    const int kB_smem = (32768 + 16 * 256) * (int)sizeof(float);   // 144 KB
    cudaFuncSetAttribute(core_kernel,
                         cudaFuncAttributeMaxDynamicSharedMemorySize, kB_smem);
    core_kernel<<<148, 512, kB_smem>>>(N);

    vout_kernel<<<(N + 7) / 8, 256>>>(Uo, out, N);
}